// round 15
// baseline (speedup 1.0000x reference)
#include <cuda_runtime.h>

#define BSEQ 512
#define LSEQ 512
#define AA   20
#define CCH  8
#define NREST 8
#define NPRE 9

#define CP_ASYNC16(smem_u32, gptr) \
    asm volatile("cp.async.cg.shared.global [%0], [%1], 16;" \
                 :: "r"(smem_u32), "l"(gptr))
#define CP_COMMIT() asm volatile("cp.async.commit_group;")
#define CP_WAIT0()  asm volatile("cp.async.wait_group 0;")

// Precomputed: effective conv map [c][p], U = I + V, and per-position residue
// indices (one byte per (b,p); 0xFF = no nonzero).
__device__ float g_W[CCH][LSEQ];
__device__ float g_U[AA * AA];
__device__ unsigned char g_idx[BSEQ * LSEQ];     // 256 KB scratch

struct PreShared {                    // 22528 B
    float bufA[CCH][256];
    float bufB[CCH][256];
    float wsh[NREST * CCH * CCH * 3];
};
struct XShared {                      // 20736 B
    float nat[256 * AA];
    unsigned char sidx[256];
};
union K1Shared { PreShared pre; XShared xs; };

// Adjoint of one conv(3,pad1)+avgpool(2) layer, block-cooperative.
template<int LEN2>
__device__ __forceinline__ void adj_layer(const float (*cur)[256],
                                          float (*nxt)[256],
                                          const float* __restrict__ w) {
    for (int idx = threadIdx.x; idx < CCH * LEN2; idx += 256) {
        const int i = idx / LEN2;
        const int p = idx % LEN2;
        float acc = 0.f;
        #pragma unroll
        for (int o = 0; o < CCH; ++o) {
            #pragma unroll
            for (int k = 0; k < 3; ++k) {
                const int q = p - k + 1;
                if (q >= 0 && q < LEN2)
                    acc += w[(o * CCH + i) * 3 + k] * 0.5f * cur[o][q >> 1];
            }
        }
        nxt[i][p] = acc;
    }
    __syncthreads();
}

// ---------------------------------------------------------------------------
// Kernel 1 (primary): blocks 0..7 -> W_eff channels (conv+pool adjoint);
// block 8 -> U; blocks 9..1032 -> stream one 20KB x chunk and emit argmax
// indices. The x stream is W-independent, so it runs fully parallel with the
// precompute — no waits anywhere in this kernel.
// ---------------------------------------------------------------------------
__global__ void __launch_bounds__(256, 7)
k1_kernel(const float* __restrict__ x,
          const float* __restrict__ lpm,
          const float* __restrict__ pm,
          const float* __restrict__ w_first,
          const float* __restrict__ w_rest) {
#if __CUDA_ARCH__ >= 900
    cudaTriggerProgrammaticLaunchCompletion();
#endif
    __shared__ K1Shared sh;
    const int blk = blockIdx.x;
    const int tid = threadIdx.x;

    if (blk >= NPRE) {
        // ---- x block: cp.async 20KB chunk -> argmax per position ----------
        XShared& xs = sh.xs;
        const int xb = blk - NPRE;           // 0..1023
        {
            const unsigned nb =
                (unsigned)__cvta_generic_to_shared(xs.nat)
                + (unsigned)tid * 16u;
            const char* xg = reinterpret_cast<const char*>(x)
                           + (size_t)xb * 20480 + (size_t)tid * 16;
            #pragma unroll
            for (int it = 0; it < 5; ++it)
                CP_ASYNC16(nb + it * 4096u, xg + it * 4096);
            CP_COMMIT();
        }
        CP_WAIT0();
        __syncthreads();

        // Scan row p = tid (20 floats, 5x LDS.128; <=4-way conflicts, cheap).
        {
            const float4* row =
                reinterpret_cast<const float4*>(&xs.nat[tid * AA]);
            int idx = -1;
            #pragma unroll
            for (int v = 0; v < 5; ++v) {
                const float4 f = row[v];
                if (f.x != 0.f) idx = v * 4 + 0;
                if (f.y != 0.f) idx = v * 4 + 1;
                if (f.z != 0.f) idx = v * 4 + 2;
                if (f.w != 0.f) idx = v * 4 + 3;
            }
            xs.sidx[tid] = (unsigned char)idx;   // -1 -> 0xFF
        }
        __syncthreads();
        if (tid < 16)
            reinterpret_cast<uint4*>(&g_idx[(size_t)xb * 256])[tid] =
                reinterpret_cast<const uint4*>(xs.sidx)[tid];
    } else if (blk < CCH) {
        // ---- W_eff channel via the conv+pool adjoint -----------------------
        PreShared& ps = sh.pre;
        for (int i = tid; i < NREST * CCH * CCH * 3; i += 256)
            ps.wsh[i] = w_rest[i];
        if (tid < CCH) ps.bufA[tid][0] = (tid == blk) ? 1.f : 0.f;
        __syncthreads();

        float (*cur)[256] = ps.bufA;
        float (*nxt)[256] = ps.bufB;
        float (*tmp)[256];
        #define STEP(L2, LI) \
            adj_layer<L2>(cur, nxt, ps.wsh + (LI) * 192); \
            tmp = cur; cur = nxt; nxt = tmp;
        STEP(2, 7)  STEP(4, 6)  STEP(8, 5)   STEP(16, 4)
        STEP(32, 3) STEP(64, 2) STEP(128, 1) STEP(256, 0)
        #undef STEP

        for (int p = tid; p < LSEQ; p += 256) {
            float acc = 0.f;
            #pragma unroll
            for (int o = 0; o < CCH; ++o) {
                #pragma unroll
                for (int k = 0; k < 3; ++k) {
                    const int q = p - k + 1;
                    if (q >= 0 && q < LSEQ)
                        acc += w_first[o * 3 + k] * 0.5f * cur[o][q >> 1];
                }
            }
            g_W[blk][p] = acc;               // [c][p]
        }
    } else {
        // ---- U[a][i] = delta(a,i) + V[a][i] --------------------------------
        for (int idx = tid; idx < AA * AA; idx += 256) {
            const int a = idx / AA, i = idx % AA;
            float v = (a == i) ? 1.f : 0.f;
            if (i != a && i != AA - 1) {
                const int r = (a < i) ? a : i;
                const int c = (a < i) ? i : a;
                float l = lpm[r * AA + c];
                l = fminf(fmaxf(l, 1e-3f), 1.f);
                v = l * pm[r * AA + c];
            }
            g_U[idx] = v;
        }
    }
}

// ---------------------------------------------------------------------------
// Kernel 2 (secondary, PDL): one block per sequence. Read 512 idx bytes +
// 16KB W (L2-hot), scatter-add g[a][c] += W[c][p] via smem atomics, then the
// U epilogue with plain stores (no out zeroing, no global atomics).
// ---------------------------------------------------------------------------
__global__ void __launch_bounds__(256, 7)
k2_kernel(float* __restrict__ out) {
    __shared__ float W_sh[CCH * LSEQ];        // 16384 B
    __shared__ float gacc[AA * CCH];
    __shared__ unsigned char sidx[LSEQ];

    const int b   = blockIdx.x;
    const int tid = threadIdx.x;

#if __CUDA_ARCH__ >= 900
    cudaGridDependencySynchronize();
#endif

    // Stage W [8][512] (1024 float4) and this sequence's 512 idx bytes.
    {
        const float4* Wg = reinterpret_cast<const float4*>(g_W);
        float4* Ws = reinterpret_cast<float4*>(W_sh);
        #pragma unroll
        for (int it = 0; it < 4; ++it)
            Ws[tid + it * 256] = Wg[tid + it * 256];
        if (tid < 32)
            reinterpret_cast<uint4*>(sidx)[tid] =
                reinterpret_cast<const uint4*>(&g_idx[(size_t)b * 512])[tid];
    }
    if (tid < AA * CCH) gacc[tid] = 0.f;
    __syncthreads();

    // Scatter: 2 positions per thread, 8 channels each.
    #pragma unroll
    for (int k = 0; k < 2; ++k) {
        const int p = tid + k * 256;
        const int a = sidx[p];
        if (a < AA) {
            #pragma unroll
            for (int c = 0; c < CCH; ++c)
                atomicAdd(&gacc[a * CCH + c], W_sh[c * LSEQ + p]);
        }
    }
    __syncthreads();

    // out[b,i,c] = sum_a U[a][i] * g[a][c]
    if (tid < AA * CCH) {
        const int i = tid >> 3;
        const int c = tid & 7;
        float r = 0.f;
        #pragma unroll
        for (int a = 0; a < AA; ++a)
            r += __ldg(&g_U[a * AA + i]) * gacc[a * CCH + c];
        out[(size_t)b * (AA * CCH) + tid] = r;
    }
}

// ---------------------------------------------------------------------------
extern "C" void kernel_launch(void* const* d_in, const int* in_sizes, int n_in,
                              void* d_out, int out_size) {
    const float* x       = (const float*)d_in[0];
    const float* lpm     = (const float*)d_in[2];
    const float* pm      = (const float*)d_in[3];
    const float* w_first = (const float*)d_in[4];
    const float* w_rest  = (const float*)d_in[5];
    float* out = (float*)d_out;

    // Primary: x->idx stream (1024 blocks) || W/U precompute (9 blocks).
    k1_kernel<<<NPRE + BSEQ * 2, 256>>>(x, lpm, pm, w_first, w_rest);

    // Secondary (PDL): tiny idx-driven scatter + epilogue.
    cudaLaunchConfig_t cfg = {};
    cfg.gridDim  = dim3(BSEQ, 1, 1);
    cfg.blockDim = dim3(256, 1, 1);
    cfg.dynamicSmemBytes = 0;
    cfg.stream = 0;
    cudaLaunchAttribute attrs[1];
    attrs[0].id = cudaLaunchAttributeProgrammaticStreamSerialization;
    attrs[0].val.programmaticStreamSerializationAllowed = 1;
    cfg.attrs = attrs;
    cfg.numAttrs = 1;
    cudaLaunchKernelEx(&cfg, k2_kernel, out);
}

// round 16
// speedup vs baseline: 2.0195x; 2.0195x over previous
#include <cuda_runtime.h>
#include <cuda_bf16.h>

#define BSEQ 512
#define LSEQ 512
#define AA   20
#define CCH  8
#define NREST 8

#define MMA_BF16(C, A, B) \
    asm volatile("mma.sync.aligned.m16n8k16.row.col.f32.bf16.bf16.f32 " \
                 "{%0,%1,%2,%3}, {%4,%5,%6,%7}, {%8,%9}, {%0,%1,%2,%3};" \
                 : "+f"((C)[0]), "+f"((C)[1]), "+f"((C)[2]), "+f"((C)[3]) \
                 : "r"((A)[0]), "r"((A)[1]), "r"((A)[2]), "r"((A)[3]), \
                   "r"((B)[0]), "r"((B)[1]))

#define MBAR_INIT(mbar, cnt) \
    asm volatile("mbarrier.init.shared.b64 [%0], %1;" \
                 :: "r"(mbar), "r"(cnt) : "memory")
#define MBAR_EXPECT_TX(mbar, bytes) \
    asm volatile("mbarrier.arrive.expect_tx.shared.b64 _, [%0], %1;" \
                 :: "r"(mbar), "r"(bytes) : "memory")
#define BULK_G2S(dst, src, bytes, mbar) \
    asm volatile("cp.async.bulk.shared::cta.global.mbarrier::complete_tx::bytes " \
                 "[%0], [%1], %2, [%3];" \
                 :: "r"(dst), "l"(src), "r"(bytes), "r"(mbar) : "memory")
#define MBAR_WAIT(mbar, parity) do { \
    unsigned _done = 0; \
    while (!_done) { \
        asm volatile("{\n\t.reg .pred p;\n\t" \
                     "mbarrier.try_wait.parity.acquire.cta.shared::cta.b64 " \
                     "p, [%1], %2, 0x989680;\n\t" \
                     "selp.b32 %0, 1, 0, p;\n\t}" \
                     : "=r"(_done) : "r"(mbar), "r"(parity) : "memory"); \
    } \
} while (0)

// Precomputed: W_eff split into bf16 hi/lo pairs, and U = I + V.
__device__ __nv_bfloat16 g_Whi[CCH][LSEQ];
__device__ __nv_bfloat16 g_Wlo[CCH][LSEQ];
__device__ float g_U[AA * AA];

// ---------------------------------------------------------------------------
// Precompute kernel (primary, PDL trigger at entry). Blocks 0..7 -> one W_eff
// channel via the conv+pool adjoint (bf16 hi/lo); block 8 -> U;
// blocks 9..168 -> zero out.
// ---------------------------------------------------------------------------
template<int LEN2>
__device__ __forceinline__ void adj_layer(const float (*cur)[256],
                                          float (*nxt)[256],
                                          const float* __restrict__ w) {
    for (int idx = threadIdx.x; idx < CCH * LEN2; idx += 256) {
        const int i = idx / LEN2;
        const int p = idx % LEN2;
        float acc = 0.f;
        #pragma unroll
        for (int o = 0; o < CCH; ++o) {
            #pragma unroll
            for (int k = 0; k < 3; ++k) {
                const int q = p - k + 1;
                if (q >= 0 && q < LEN2)
                    acc += w[(o * CCH + i) * 3 + k] * 0.5f * cur[o][q >> 1];
            }
        }
        nxt[i][p] = acc;
    }
    __syncthreads();
}

__global__ void __launch_bounds__(256)
precompute_kernel(const float* __restrict__ lpm,
                  const float* __restrict__ pm,
                  const float* __restrict__ w_first,
                  const float* __restrict__ w_rest,
                  float* __restrict__ out) {
#if __CUDA_ARCH__ >= 900
    cudaTriggerProgrammaticLaunchCompletion();
#endif
    const int blk = blockIdx.x;
    const int tid = threadIdx.x;

    if (blk < CCH) {
        __shared__ float bufA[CCH][256];
        __shared__ float bufB[CCH][256];
        __shared__ float wsh[NREST * CCH * CCH * 3];

        for (int i = tid; i < NREST * CCH * CCH * 3; i += 256)
            wsh[i] = w_rest[i];
        if (tid < CCH) bufA[tid][0] = (tid == blk) ? 1.f : 0.f;
        __syncthreads();

        float (*cur)[256] = bufA;
        float (*nxt)[256] = bufB;
        float (*tmp)[256];
        #define STEP(L2, LI) \
            adj_layer<L2>(cur, nxt, wsh + (LI) * 192); \
            tmp = cur; cur = nxt; nxt = tmp;
        STEP(2, 7)  STEP(4, 6)  STEP(8, 5)   STEP(16, 4)
        STEP(32, 3) STEP(64, 2) STEP(128, 1) STEP(256, 0)
        #undef STEP

        for (int p = tid; p < LSEQ; p += 256) {
            float acc = 0.f;
            #pragma unroll
            for (int o = 0; o < CCH; ++o) {
                #pragma unroll
                for (int k = 0; k < 3; ++k) {
                    const int q = p - k + 1;
                    if (q >= 0 && q < LSEQ)
                        acc += w_first[o * 3 + k] * 0.5f * cur[o][q >> 1];
                }
            }
            const __nv_bfloat16 hi = __float2bfloat16(acc);
            g_Whi[blk][p] = hi;
            g_Wlo[blk][p] = __float2bfloat16(acc - __bfloat162float(hi));
        }
    } else if (blk == CCH) {
        // U[a][i] = delta(a,i) + V[a][i]
        for (int idx = tid; idx < AA * AA; idx += 256) {
            const int a = idx / AA, i = idx % AA;
            float v = (a == i) ? 1.f : 0.f;
            if (i != a && i != AA - 1) {
                const int r = (a < i) ? a : i;
                const int c = (a < i) ? i : a;
                float l = lpm[r * AA + c];
                l = fminf(fmaxf(l, 1e-3f), 1.f);
                v = l * pm[r * AA + c];
            }
            g_U[idx] = v;
        }
    } else {
        const int z = blk - (CCH + 1);          // 0..159
        if (tid < 128)
            reinterpret_cast<float4*>(out)[z * 128 + tid] =
                make_float4(0.f, 0.f, 0.f, 0.f);
    }
}

// pack two fp32 into bf16x2 (lo in low half)
__device__ __forceinline__ unsigned pack_bf2(float lo, float hi) {
    __nv_bfloat162 u = __floats2bfloat162_rn(lo, hi);
    return *reinterpret_cast<unsigned*>(&u);
}

// ---------------------------------------------------------------------------
// Main kernel (secondary, PDL): grid 1024 = 512 sequences x 2 halves.
// ONE cp.async.bulk (20KB) per block replaces 1280 cp.async ops -> the
// per-16B LSU issue floor disappears; the stream rides the bulk-DMA path.
// Then: gridsync -> B-frag LDG (L2-hot) -> mbarrier wait -> A-from-nat MMA
// (R14-proven) -> cross-warp reduce -> U epilogue -> atomicAdd.
// ---------------------------------------------------------------------------
__global__ void __launch_bounds__(256, 7)
main_kernel(const float* __restrict__ x, float* __restrict__ out) {
    __shared__ __align__(16) float nat[256 * AA];   // 20480 B
    __shared__ float Dp[8][32][8];                  //  8192 B
    __shared__ float g_sh[AA][CCH];
    __shared__ __align__(8) unsigned long long mbar;

    const int bi   = blockIdx.x;
    const int b    = bi >> 1;
    const int half = bi & 1;
    const int tid  = threadIdx.x;
    const int lane = tid & 31;
    const int w    = tid >> 5;

    const unsigned mb = (unsigned)__cvta_generic_to_shared(&mbar);

    // ---- Init mbarrier and issue ONE 20KB bulk copy -------------------------
    if (tid == 0) MBAR_INIT(mb, 1);
    __syncthreads();
    if (tid == 0) {
        MBAR_EXPECT_TX(mb, 20480u);
        const char* src = reinterpret_cast<const char*>(x)
                        + (size_t)b * 40960 + half * 20480;
        BULK_G2S((unsigned)__cvta_generic_to_shared(nat), src, 20480u, mb);
    }

    // ---- Wait for precompute; the bulk copy flies under this ----------------
#if __CUDA_ARCH__ >= 900
    cudaGridDependencySynchronize();
#endif

    // ---- B fragments via LDG.32 from L2-hot g_Whi / g_Wlo -------------------
    // m16n8k16 col B: lane l -> n = l>>2, k pairs {2(l&3), +1} and {+8, +9}.
    const int kbase = w * 32;
    const int c_n  = lane >> 2;
    const int kq   = 2 * (lane & 3);
    unsigned Bh[2][2], Bl[2][2];
    #pragma unroll
    for (int ks = 0; ks < 2; ++ks) {
        const int kcol = half * 256 + kbase + ks * 16 + kq;
        Bh[ks][0] = *reinterpret_cast<const unsigned*>(&g_Whi[c_n][kcol]);
        Bh[ks][1] = *reinterpret_cast<const unsigned*>(&g_Whi[c_n][kcol + 8]);
        Bl[ks][0] = *reinterpret_cast<const unsigned*>(&g_Wlo[c_n][kcol]);
        Bl[ks][1] = *reinterpret_cast<const unsigned*>(&g_Wlo[c_n][kcol + 8]);
    }

    // ---- Wait for the bulk copy (acquire orders the smem reads) -------------
    MBAR_WAIT(mb, 0u);

    // ---- A fragments straight from nat; 8 MMAs (R14-proven layout) ----------
    const int r0 = lane >> 2;
    float C0[4] = {0.f, 0.f, 0.f, 0.f};
    float C1[4] = {0.f, 0.f, 0.f, 0.f};

    #pragma unroll
    for (int ks = 0; ks < 2; ++ks) {
        const int cb = kbase + ks * 16 + kq;    // local position (col k)
        const float* n0 = &nat[cb * AA];
        unsigned A0[4];
        A0[0] = pack_bf2(n0[r0],              n0[AA + r0]);
        A0[1] = pack_bf2(n0[8 + r0],          n0[AA + 8 + r0]);
        A0[2] = pack_bf2(n0[8 * AA + r0],     n0[9 * AA + r0]);
        A0[3] = pack_bf2(n0[8 * AA + 8 + r0], n0[9 * AA + 8 + r0]);
        unsigned A1[4] = {0u, 0u, 0u, 0u};
        if (r0 < 4) {
            A1[0] = pack_bf2(n0[16 + r0],          n0[AA + 16 + r0]);
            A1[2] = pack_bf2(n0[8 * AA + 16 + r0], n0[9 * AA + 16 + r0]);
        }
        MMA_BF16(C0, A0, Bh[ks]);
        MMA_BF16(C0, A0, Bl[ks]);      // W = hi + lo, same accumulator
        MMA_BF16(C1, A1, Bh[ks]);
        MMA_BF16(C1, A1, Bl[ks]);
    }

    // ---- Park per-warp partials; deterministic 8-way cross-warp reduce ------
    {
        const int q2 = (lane & 3) * 2, tr = lane >> 2;
        *reinterpret_cast<float2*>(&Dp[w][tr     ][q2]) = make_float2(C0[0], C0[1]);
        *reinterpret_cast<float2*>(&Dp[w][tr +  8][q2]) = make_float2(C0[2], C0[3]);
        *reinterpret_cast<float2*>(&Dp[w][tr + 16][q2]) = make_float2(C1[0], C1[1]);
        *reinterpret_cast<float2*>(&Dp[w][tr + 24][q2]) = make_float2(C1[2], C1[3]);
    }
    __syncthreads();

    if (tid < AA * CCH) {
        const int a = tid >> 3, c = tid & 7;
        float sum = 0.f;
        #pragma unroll
        for (int ww = 0; ww < 8; ++ww) sum += Dp[ww][a][c];
        g_sh[a][c] = sum;
    }
    __syncthreads();

    // out[b,i,c] += sum_a U[a][i] * g[a][c]   (2 halves combine via atomics)
    if (tid < AA * CCH) {
        const int i = tid >> 3;
        const int c = tid & 7;
        float r = 0.f;
        #pragma unroll
        for (int a = 0; a < AA; ++a)
            r += __ldg(&g_U[a * AA + i]) * g_sh[a][c];
        atomicAdd(&out[(size_t)b * (AA * CCH) + tid], r);
    }
}

// ---------------------------------------------------------------------------
extern "C" void kernel_launch(void* const* d_in, const int* in_sizes, int n_in,
                              void* d_out, int out_size) {
    const float* x       = (const float*)d_in[0];
    const float* lpm     = (const float*)d_in[2];
    const float* pm      = (const float*)d_in[3];
    const float* w_first = (const float*)d_in[4];
    const float* w_rest  = (const float*)d_in[5];
    float* out = (float*)d_out;

    // Primary: precompute W hi/lo + U, zero out; triggers PDL at entry.
    precompute_kernel<<<CCH + 1 + 160, 256>>>(lpm, pm, w_first, w_rest, out);

    // Secondary: PDL launch — bulk copy flies while primary still runs.
    cudaLaunchConfig_t cfg = {};
    cfg.gridDim  = dim3(BSEQ * 2, 1, 1);
    cfg.blockDim = dim3(256, 1, 1);
    cfg.dynamicSmemBytes = 0;
    cfg.stream = 0;
    cudaLaunchAttribute attrs[1];
    attrs[0].id = cudaLaunchAttributeProgrammaticStreamSerialization;
    attrs[0].val.programmaticStreamSerializationAllowed = 1;
    cfg.attrs = attrs;
    cfg.numAttrs = 1;
    cudaLaunchKernelEx(&cfg, main_kernel, x, (float*)d_out);
}